// round 3
// baseline (speedup 1.0000x reference)
#include <cuda_runtime.h>
#include <cstdint>
#include <cstddef>

// ---------------- problem constants ----------------
static constexpr int Bb  = 4;
static constexpr int L   = 2048;
static constexpr int DM  = 1024;          // d_model
static constexpr int DI  = 2048;          // d_inner
static constexpr int DS  = 16;            // d_state
static constexpr int DTR = 64;            // dt_rank
static constexpr int ROWS = Bb * L;       // 8192
static constexpr int DBC = DTR + 2 * DS;  // 96

// ---------------- scratch (device globals, no allocations) ----------------
__device__ float g_sc[Bb * DM];                         // silu(c)
__device__ float g_mod[Bb * 3 * DM];                    // scale|shift|gate
__device__ float g_h[(size_t)ROWS * DM];                // LN-modulated input
__device__ float g_xz[(size_t)ROWS * 2 * DI];           // x@W_in  (xm | z)
__device__ float g_xc[(size_t)ROWS * DI];               // conv+silu
__device__ float g_dbc[(size_t)ROWS * DBC];             // dt | B | C
__device__ float g_delta[(size_t)ROWS * DI];            // softplus(dt@W_dt+b)
__device__ float g_ymul[(size_t)ROWS * DI];             // (scan + u*D)*silu(z)

// ---------------- small kernels ----------------
__global__ void k_silu_c(const float* __restrict__ c) {
    int i = blockIdx.x * blockDim.x + threadIdx.x;
    if (i < Bb * DM) {
        float v = c[i];
        g_sc[i] = v / (1.f + __expf(-v));
    }
}

// mod[b][j] = b_ada[j] + sum_k silu(c)[b][k] * W_ada[k][j]
__global__ void k_ada(const float* __restrict__ W, const float* __restrict__ bias) {
    int j = blockIdx.x * blockDim.x + threadIdx.x;   // 0..3071
    int b = blockIdx.y;
    const float* sc = g_sc + b * DM;
    float a0 = 0.f, a1 = 0.f, a2 = 0.f, a3 = 0.f;
    for (int k = 0; k < DM; k += 4) {
        a0 += sc[k]     * W[(size_t)k       * (3 * DM) + j];
        a1 += sc[k + 1] * W[(size_t)(k + 1) * (3 * DM) + j];
        a2 += sc[k + 2] * W[(size_t)(k + 2) * (3 * DM) + j];
        a3 += sc[k + 3] * W[(size_t)(k + 3) * (3 * DM) + j];
    }
    g_mod[b * 3 * DM + j] = bias[j] + ((a0 + a1) + (a2 + a3));
}

// LayerNorm(no affine) + (1+scale)*xn + shift   -> g_h
__global__ void k_ln(const float* __restrict__ x) {
    int row = blockIdx.x;
    int b = row >> 11;
    const float4* xr = (const float4*)(x + (size_t)row * DM);
    float4 v = xr[threadIdx.x];                      // 256 thr * 4 = 1024
    float s = v.x + v.y + v.z + v.w;
    float q = v.x * v.x + v.y * v.y + v.z * v.z + v.w * v.w;
    #pragma unroll
    for (int o = 16; o; o >>= 1) {
        s += __shfl_xor_sync(0xffffffffu, s, o);
        q += __shfl_xor_sync(0xffffffffu, q, o);
    }
    __shared__ float ss[8], sq[8];
    int w = threadIdx.x >> 5;
    if ((threadIdx.x & 31) == 0) { ss[w] = s; sq[w] = q; }
    __syncthreads();
    s = 0.f; q = 0.f;
    #pragma unroll
    for (int i = 0; i < 8; i++) { s += ss[i]; q += sq[i]; }
    float mean = s * (1.f / DM);
    float var  = q * (1.f / DM) - mean * mean;
    float rstd = rsqrtf(var + 1e-6f);
    int col = threadIdx.x * 4;
    float4 sc4 = *(const float4*)(g_mod + b * 3 * DM + col);
    float4 sh4 = *(const float4*)(g_mod + b * 3 * DM + DM + col);
    float4 o;
    o.x = (v.x - mean) * rstd * (1.f + sc4.x) + sh4.x;
    o.y = (v.y - mean) * rstd * (1.f + sc4.y) + sh4.y;
    o.z = (v.z - mean) * rstd * (1.f + sc4.z) + sh4.z;
    o.w = (v.w - mean) * rstd * (1.f + sc4.w) + sh4.w;
    *(float4*)(g_h + (size_t)row * DM + col) = o;
}

// causal depthwise conv (kernel 4) + silu :  g_xz[:, :DI] -> g_xc
__global__ void k_conv(const float* __restrict__ cw, const float* __restrict__ cb) {
    int i = blockIdx.x * blockDim.x + threadIdx.x;
    if (i >= ROWS * DI) return;
    int d = i & (DI - 1);
    int row = i >> 11;          // b*L + l
    int l = row & (L - 1);
    float4 w = *(const float4*)(cw + 4 * d);
    size_t base = (size_t)row * (2 * DI) + d;
    float acc = cb[d] + g_xz[base] * w.w;
    if (l >= 1) acc += g_xz[base - 1 * (2 * DI)] * w.z;
    if (l >= 2) acc += g_xz[base - 2 * (2 * DI)] * w.y;
    if (l >= 3) acc += g_xz[base - 3 * (2 * DI)] * w.x;
    float sil = acc / (1.f + __expf(-acc));
    g_xc[(size_t)row * DI + d] = sil;
}

// selective scan: one thread per (b, d) channel, 16 states in registers.
// fused epilogue: y = (scan + u*D_skip) * silu(z)  -> g_ymul
__global__ void k_scan(const float* __restrict__ Alog, const float* __restrict__ Dskip) {
    int t = blockIdx.x * blockDim.x + threadIdx.x;   // 0..8191
    int b = t >> 11, d = t & (DI - 1);
    float Ar[DS];
    #pragma unroll
    for (int s = 0; s < DS; s++) Ar[s] = -__expf(Alog[d * DS + s]);
    float h[DS];
    #pragma unroll
    for (int s = 0; s < DS; s++) h[s] = 0.f;
    float Dsk = Dskip[d];
    const float* dbcBC = g_dbc + (size_t)(b * L) * DBC + DTR;
    size_t base = (size_t)(b * L) * DI + d;
    size_t zb   = (size_t)(b * L) * (2 * DI) + DI + d;
    for (int l = 0; l < L; l++) {
        float delta = g_delta[base];
        float u     = g_xc[base];
        float z     = g_xz[zb];
        const float4* p = (const float4*)(dbcBC + (size_t)l * DBC);
        float4 B0 = p[0], B1 = p[1], B2 = p[2], B3 = p[3];
        float4 C0 = p[4], C1 = p[5], C2 = p[6], C3 = p[7];
        float Bv[16] = {B0.x,B0.y,B0.z,B0.w, B1.x,B1.y,B1.z,B1.w,
                        B2.x,B2.y,B2.z,B2.w, B3.x,B3.y,B3.z,B3.w};
        float Cv[16] = {C0.x,C0.y,C0.z,C0.w, C1.x,C1.y,C1.z,C1.w,
                        C2.x,C2.y,C2.z,C2.w, C3.x,C3.y,C3.z,C3.w};
        float du = delta * u;
        float y = 0.f;
        #pragma unroll
        for (int s = 0; s < DS; s++) {
            float dA = __expf(delta * Ar[s]);
            h[s] = fmaf(dA, h[s], du * Bv[s]);
            y = fmaf(h[s], Cv[s], y);
        }
        float yy = y + u * Dsk;
        float sig = 1.f / (1.f + __expf(-z));
        g_ymul[base] = yy * (z * sig);
        base += DI;
        zb   += 2 * DI;
    }
}

// ---------------- tiled SGEMM (row-major) with fused epilogues ----------------
// EPI 0: C = acc
// EPI 1: C = softplus(acc + bias[n])
// EPI 2: C = res[r][n] + gate[b][n] * acc   (gate = g_mod[b][2*DM + n], b = r>>11)
template <int BM, int BN, int BK, int TM, int TN, int EPI>
__global__ __launch_bounds__((BM / TM) * (BN / TN))
void sgemm(int M, int N, int K, int lda, int ldb, int ldc,
           const float* __restrict__ A, const float* __restrict__ B,
           float* __restrict__ C,
           const float* __restrict__ bias, const float* __restrict__ res) {
    constexpr int THREADS = (BM / TM) * (BN / TN);
    __shared__ float As[BK][BM];
    __shared__ float Bs[BK][BN];
    const int tid = threadIdx.x;
    const int tx = tid % (BN / TN);
    const int ty = tid / (BN / TN);
    const int rowBase = blockIdx.y * BM;
    const int colBase = blockIdx.x * BN;
    const float* Ablk = A + (size_t)rowBase * lda;
    const float* Bblk = B + colBase;
    float acc[TM][TN];
    #pragma unroll
    for (int i = 0; i < TM; i++)
        #pragma unroll
        for (int j = 0; j < TN; j++) acc[i][j] = 0.f;

    for (int k0 = 0; k0 < K; k0 += BK) {
        // A tile: BM x BK, stored transposed As[k][m]
        #pragma unroll
        for (int i = tid; i < BM * BK / 4; i += THREADS) {
            int m  = i / (BK / 4);
            int kk = (i % (BK / 4)) * 4;
            float4 v = *(const float4*)(Ablk + (size_t)m * lda + k0 + kk);
            As[kk + 0][m] = v.x;
            As[kk + 1][m] = v.y;
            As[kk + 2][m] = v.z;
            As[kk + 3][m] = v.w;
        }
        // B tile: BK x BN
        #pragma unroll
        for (int i = tid; i < BK * BN / 4; i += THREADS) {
            int kk = i / (BN / 4);
            int n  = (i % (BN / 4)) * 4;
            *(float4*)(&Bs[kk][n]) = *(const float4*)(Bblk + (size_t)(k0 + kk) * ldb + n);
        }
        __syncthreads();
        #pragma unroll
        for (int kk = 0; kk < BK; kk++) {
            float ra[TM], rb[TN];
            #pragma unroll
            for (int i = 0; i < TM; i++) ra[i] = As[kk][ty * TM + i];
            #pragma unroll
            for (int j = 0; j < TN; j++) rb[j] = Bs[kk][tx * TN + j];
            #pragma unroll
            for (int i = 0; i < TM; i++)
                #pragma unroll
                for (int j = 0; j < TN; j++)
                    acc[i][j] = fmaf(ra[i], rb[j], acc[i][j]);
        }
        __syncthreads();
    }

    #pragma unroll
    for (int i = 0; i < TM; i++) {
        int r = rowBase + ty * TM + i;
        #pragma unroll
        for (int j = 0; j < TN; j++) {
            int n = colBase + tx * TN + j;
            float v = acc[i][j];
            if (EPI == 1) {
                v += bias[n];
                v = (v > 20.f) ? v : log1pf(__expf(v));
            } else if (EPI == 2) {
                float g = g_mod[(r >> 11) * 3 * DM + 2 * DM + n];
                v = res[(size_t)r * ldc + n] + g * v;
            }
            C[(size_t)r * ldc + n] = v;
        }
    }
}

// ---------------- launch ----------------
extern "C" void kernel_launch(void* const* d_in, const int* in_sizes, int n_in,
                              void* d_out, int out_size) {
    const float* x      = (const float*)d_in[0];
    const float* c      = (const float*)d_in[1];
    const float* W_in   = (const float*)d_in[2];
    const float* conv_w = (const float*)d_in[3];
    const float* conv_b = (const float*)d_in[4];
    const float* W_xp   = (const float*)d_in[5];
    const float* W_dt   = (const float*)d_in[6];
    const float* b_dt   = (const float*)d_in[7];
    const float* A_log  = (const float*)d_in[8];
    const float* D_skip = (const float*)d_in[9];
    const float* W_out  = (const float*)d_in[10];
    const float* W_ada  = (const float*)d_in[11];
    const float* b_ada  = (const float*)d_in[12];
    float* out = (float*)d_out;

    float *p_h, *p_xz, *p_xc, *p_dbc, *p_delta, *p_ymul;
    cudaGetSymbolAddress((void**)&p_h,     g_h);
    cudaGetSymbolAddress((void**)&p_xz,    g_xz);
    cudaGetSymbolAddress((void**)&p_xc,    g_xc);
    cudaGetSymbolAddress((void**)&p_dbc,   g_dbc);
    cudaGetSymbolAddress((void**)&p_delta, g_delta);
    cudaGetSymbolAddress((void**)&p_ymul,  g_ymul);

    // 1) silu(c), ada modulation
    k_silu_c<<<(Bb * DM + 255) / 256, 256>>>(c);
    k_ada<<<dim3(3 * DM / 256, Bb), 256>>>(W_ada, b_ada);

    // 2) LayerNorm + scale/shift
    k_ln<<<ROWS, 256>>>(x);

    // 3) GEMM1: h @ W_in -> xz   [8192 x 4096, K=1024]
    sgemm<128, 128, 16, 8, 8, 0><<<dim3(2 * DI / 128, ROWS / 128), 256>>>(
        ROWS, 2 * DI, DM, DM, 2 * DI, 2 * DI, p_h, W_in, p_xz, nullptr, nullptr);

    // 4) depthwise causal conv + silu -> xc
    k_conv<<<(ROWS * DI) / 256, 256>>>(conv_w, conv_b);

    // 5) GEMM2: xc @ W_xproj -> dbc   [8192 x 96, K=2048]
    sgemm<64, 96, 16, 4, 6, 0><<<dim3(1, ROWS / 64), 256>>>(
        ROWS, DBC, DI, DI, DBC, DBC, p_xc, W_xp, p_dbc, nullptr, nullptr);

    // 6) delta GEMM: dbc[:, :64] @ W_dt + b_dt, softplus -> delta   [8192 x 2048, K=64]
    sgemm<128, 128, 16, 8, 8, 1><<<dim3(DI / 128, ROWS / 128), 256>>>(
        ROWS, DI, DTR, DBC, DI, DI, p_dbc, W_dt, p_delta, b_dt, nullptr);

    // 7) selective scan + skip + silu(z) gate -> ymul
    k_scan<<<256, 32>>>(A_log, D_skip);

    // 8) GEMM3: ymul @ W_out, fused residual + gate -> out   [8192 x 1024, K=2048]
    sgemm<128, 128, 16, 8, 8, 2><<<dim3(DM / 128, ROWS / 128), 256>>>(
        ROWS, DM, DI, DI, DM, DM, p_ymul, W_out, out, nullptr, x);
}

// round 7
// speedup vs baseline: 1.1468x; 1.1468x over previous
#include <cuda_runtime.h>
#include <cstdint>
#include <cstddef>

// ---------------- problem constants ----------------
static constexpr int Bb  = 4;
static constexpr int L   = 2048;
static constexpr int DM  = 1024;          // d_model
static constexpr int DI  = 2048;          // d_inner
static constexpr int DS  = 16;            // d_state
static constexpr int DTR = 64;            // dt_rank
static constexpr int ROWS = Bb * L;       // 8192
static constexpr int DBC = DTR + 2 * DS;  // 96

// ---------------- scratch (device globals, no allocations) ----------------
__device__ float g_sc[Bb * DM];                         // silu(c)
__device__ float g_mod[Bb * 3 * DM];                    // scale|shift|gate
__device__ float g_h[(size_t)ROWS * DM];                // LN-modulated input
__device__ float g_xz[(size_t)ROWS * 2 * DI];           // x@W_in  (xm | z)
__device__ float g_xc[(size_t)ROWS * DI];               // conv+silu
__device__ float g_dbc[(size_t)ROWS * DBC];             // dt | B | C
__device__ float g_delta[(size_t)ROWS * DI];            // softplus(dt@W_dt+b)
__device__ float g_ymul[(size_t)ROWS * DI];             // (scan + u*D)*silu(z)
__device__ float g_WinT[(size_t)(2 * DI) * DM];         // W_in^T  [4096][1024]
__device__ float g_WdtT[(size_t)DI * DTR];              // W_dt^T  [2048][64]
__device__ float g_WoutT[(size_t)DM * DI];              // W_out^T [1024][2048]

// ---------------- helpers ----------------
__device__ __forceinline__ uint32_t f2tf32(float f) {
    uint32_t o;
    asm("cvt.rna.tf32.f32 %0, %1;" : "=r"(o) : "f"(f));
    return o;
}
__device__ __forceinline__ float tf32f(float f) { return __uint_as_float(f2tf32(f)); }

__device__ __forceinline__ void mma_tf32(float* c, const uint32_t* a, const uint32_t* b) {
    asm volatile(
        "mma.sync.aligned.m16n8k8.row.col.f32.tf32.tf32.f32 "
        "{%0,%1,%2,%3}, {%4,%5,%6,%7}, {%8,%9}, {%0,%1,%2,%3};"
        : "+f"(c[0]), "+f"(c[1]), "+f"(c[2]), "+f"(c[3])
        : "r"(a[0]), "r"(a[1]), "r"(a[2]), "r"(a[3]), "r"(b[0]), "r"(b[1]));
}

// ---------------- small kernels ----------------
__global__ void k_silu_c(const float* __restrict__ c) {
    int i = blockIdx.x * blockDim.x + threadIdx.x;
    if (i < Bb * DM) {
        float v = c[i];
        g_sc[i] = v / (1.f + __expf(-v));
    }
}

__global__ void k_ada(const float* __restrict__ W, const float* __restrict__ bias) {
    int j = blockIdx.x * blockDim.x + threadIdx.x;
    int b = blockIdx.y;
    const float* sc = g_sc + b * DM;
    float a0 = 0.f, a1 = 0.f, a2 = 0.f, a3 = 0.f;
    for (int k = 0; k < DM; k += 4) {
        a0 += sc[k]     * W[(size_t)k       * (3 * DM) + j];
        a1 += sc[k + 1] * W[(size_t)(k + 1) * (3 * DM) + j];
        a2 += sc[k + 2] * W[(size_t)(k + 2) * (3 * DM) + j];
        a3 += sc[k + 3] * W[(size_t)(k + 3) * (3 * DM) + j];
    }
    g_mod[b * 3 * DM + j] = bias[j] + ((a0 + a1) + (a2 + a3));
}

__global__ void k_ln(const float* __restrict__ x) {
    int row = blockIdx.x;
    int b = row >> 11;
    const float4* xr = (const float4*)(x + (size_t)row * DM);
    float4 v = xr[threadIdx.x];
    float s = v.x + v.y + v.z + v.w;
    float q = v.x * v.x + v.y * v.y + v.z * v.z + v.w * v.w;
    #pragma unroll
    for (int o = 16; o; o >>= 1) {
        s += __shfl_xor_sync(0xffffffffu, s, o);
        q += __shfl_xor_sync(0xffffffffu, q, o);
    }
    __shared__ float ss[8], sq[8];
    int w = threadIdx.x >> 5;
    if ((threadIdx.x & 31) == 0) { ss[w] = s; sq[w] = q; }
    __syncthreads();
    s = 0.f; q = 0.f;
    #pragma unroll
    for (int i = 0; i < 8; i++) { s += ss[i]; q += sq[i]; }
    float mean = s * (1.f / DM);
    float var  = q * (1.f / DM) - mean * mean;
    float rstd = rsqrtf(var + 1e-6f);
    int col = threadIdx.x * 4;
    float4 sc4 = *(const float4*)(g_mod + b * 3 * DM + col);
    float4 sh4 = *(const float4*)(g_mod + b * 3 * DM + DM + col);
    float4 o;
    o.x = (v.x - mean) * rstd * (1.f + sc4.x) + sh4.x;
    o.y = (v.y - mean) * rstd * (1.f + sc4.y) + sh4.y;
    o.z = (v.z - mean) * rstd * (1.f + sc4.z) + sh4.z;
    o.w = (v.w - mean) * rstd * (1.f + sc4.w) + sh4.w;
    *(float4*)(g_h + (size_t)row * DM + col) = o;
}

__global__ void k_conv(const float* __restrict__ cw, const float* __restrict__ cb) {
    int i = blockIdx.x * blockDim.x + threadIdx.x;
    if (i >= ROWS * DI) return;
    int d = i & (DI - 1);
    int row = i >> 11;
    int l = row & (L - 1);
    float4 w = *(const float4*)(cw + 4 * d);
    size_t base = (size_t)row * (2 * DI) + d;
    float acc = cb[d] + g_xz[base] * w.w;
    if (l >= 1) acc += g_xz[base - 1 * (2 * DI)] * w.z;
    if (l >= 2) acc += g_xz[base - 2 * (2 * DI)] * w.y;
    if (l >= 3) acc += g_xz[base - 3 * (2 * DI)] * w.x;
    float sil = acc / (1.f + __expf(-acc));
    g_xc[(size_t)row * DI + d] = sil;
}

// 32x32 tiled transpose: D[C][R] = S[R][C]^T
__global__ void k_tr(const float* __restrict__ S, float* __restrict__ D, int R, int C) {
    __shared__ float t[32][33];
    int c0 = blockIdx.x * 32, r0 = blockIdx.y * 32;
    #pragma unroll
    for (int j = 0; j < 4; j++)
        t[threadIdx.y + 8 * j][threadIdx.x] =
            S[(size_t)(r0 + threadIdx.y + 8 * j) * C + c0 + threadIdx.x];
    __syncthreads();
    #pragma unroll
    for (int j = 0; j < 4; j++)
        D[(size_t)(c0 + threadIdx.y + 8 * j) * R + r0 + threadIdx.x] =
            t[threadIdx.x][threadIdx.y + 8 * j];
}

// selective scan: 4 threads per (b,d) channel, 4 states each.
__global__ void k_scan4(const float* __restrict__ Alog, const float* __restrict__ Dskip) {
    int t = blockIdx.x * blockDim.x + threadIdx.x;   // 0..32767
    int q = t & 3;
    int ch = t >> 2;                                 // 0..8191
    int b = ch >> 11, d = ch & (DI - 1);
    float Ar[4];
    #pragma unroll
    for (int s = 0; s < 4; s++) Ar[s] = -__expf(Alog[d * DS + q * 4 + s]);
    float h[4] = {0.f, 0.f, 0.f, 0.f};
    float Dsk = Dskip[d];
    const float* dbcB = g_dbc + (size_t)(b * L) * DBC + DTR + q * 4;
    size_t base = (size_t)(b * L) * DI + d;
    size_t zb   = (size_t)(b * L) * (2 * DI) + DI + d;
    for (int l = 0; l < L; l++) {
        float delta = g_delta[base];
        float u     = g_xc[base];
        float4 Bv = *(const float4*)(dbcB + (size_t)l * DBC);
        float4 Cv = *(const float4*)(dbcB + (size_t)l * DBC + DS);
        float du = delta * u;
        float y = 0.f;
        float dA0 = __expf(delta * Ar[0]);
        float dA1 = __expf(delta * Ar[1]);
        float dA2 = __expf(delta * Ar[2]);
        float dA3 = __expf(delta * Ar[3]);
        h[0] = fmaf(dA0, h[0], du * Bv.x); y = fmaf(h[0], Cv.x, y);
        h[1] = fmaf(dA1, h[1], du * Bv.y); y = fmaf(h[1], Cv.y, y);
        h[2] = fmaf(dA2, h[2], du * Bv.z); y = fmaf(h[2], Cv.z, y);
        h[3] = fmaf(dA3, h[3], du * Bv.w); y = fmaf(h[3], Cv.w, y);
        y += __shfl_xor_sync(0xffffffffu, y, 1);
        y += __shfl_xor_sync(0xffffffffu, y, 2);
        if (q == 0) {
            float z = g_xz[zb];
            float yy = y + u * Dsk;
            float sig = 1.f / (1.f + __expf(-z));
            g_ymul[base] = yy * (z * sig);
        }
        base += DI;
        zb   += 2 * DI;
    }
}

// ---------------- tf32 mma.sync GEMM: C[M,N] = A[M,K] * Bt[N,K]^T ----------------
// CTA tile 128x128, BK=32. 8 warps (2 x 4), each warp 64x32 via m16n8k8.
// smem: per-8-col interleave perm [0,4,1,5,2,6,3,7] -> every fragment pair is
// one aligned 64-bit LDS; stride padded to 34 floats (conflict-free).
// EPI 0: plain   EPI 1: softplus(acc + bias[n])   EPI 2: res + gate*acc
template <int EPI>
__global__ __launch_bounds__(256)
void gemm_mma(int K, int lda, int ldb, int ldc,
              const float* __restrict__ A, const float* __restrict__ Bt,
              float* __restrict__ C,
              const float* __restrict__ bias, const float* __restrict__ res) {
    constexpr int SA = 34;
    __shared__ float sA[128 * SA];
    __shared__ float sB[128 * SA];
    const int tid = threadIdx.x;
    const int wid = tid >> 5, lane = tid & 31;
    const int g = lane >> 2, t4 = lane & 3;
    const int wm = wid & 1, wn = wid >> 1;
    const int rowBase = blockIdx.y * 128, colBase = blockIdx.x * 128;
    const float* Ab = A  + (size_t)rowBase * lda;
    const float* Bp = Bt + (size_t)colBase * ldb;

    float acc[4][4][4];
    #pragma unroll
    for (int m = 0; m < 4; m++)
        #pragma unroll
        for (int n = 0; n < 4; n++)
            #pragma unroll
            for (int e = 0; e < 4; e++) acc[m][n][e] = 0.f;

    int er[4], ev[4];
    #pragma unroll
    for (int i = 0; i < 4; i++) {
        int e = tid + i * 256;
        er[i] = e >> 3;          // row 0..127
        ev[i] = e & 7;           // float4 slot 0..7 (covers 32 k)
    }

    float4 ra[4], rb[4];
    #pragma unroll
    for (int i = 0; i < 4; i++) {
        ra[i] = *(const float4*)(Ab + (size_t)er[i] * lda + ev[i] * 4);
        rb[i] = *(const float4*)(Bp + (size_t)er[i] * ldb + ev[i] * 4);
    }

    const int nk = K >> 5;
    for (int k = 0; k < nk; k++) {
        // STS with tf32 round + interleave perm: orig col c -> 2*(c%4) + c/4
        #pragma unroll
        for (int i = 0; i < 4; i++) {
            int base = er[i] * SA + (ev[i] >> 1) * 8 + (ev[i] & 1);
            sA[base + 0] = tf32f(ra[i].x);
            sA[base + 2] = tf32f(ra[i].y);
            sA[base + 4] = tf32f(ra[i].z);
            sA[base + 6] = tf32f(ra[i].w);
            sB[base + 0] = tf32f(rb[i].x);
            sB[base + 2] = tf32f(rb[i].y);
            sB[base + 4] = tf32f(rb[i].z);
            sB[base + 6] = tf32f(rb[i].w);
        }
        __syncthreads();
        if (k + 1 < nk) {
            int k0 = (k + 1) * 32;
            #pragma unroll
            for (int i = 0; i < 4; i++) {
                ra[i] = *(const float4*)(Ab + (size_t)er[i] * lda + k0 + ev[i] * 4);
                rb[i] = *(const float4*)(Bp + (size_t)er[i] * ldb + k0 + ev[i] * 4);
            }
        }
        #pragma unroll
        for (int kk = 0; kk < 4; kk++) {
            uint32_t af[4][4];
            uint32_t bf[4][2];
            #pragma unroll
            for (int m = 0; m < 4; m++) {
                const float* p0 = &sA[(wm * 64 + m * 16 + g) * SA + kk * 8 + 2 * t4];
                float2 lo = *(const float2*)p0;            // a0 (g, t4), a2 (g, t4+4)
                float2 hi = *(const float2*)(p0 + 8 * SA); // a1 (g+8, t4), a3 (g+8, t4+4)
                af[m][0] = __float_as_uint(lo.x);
                af[m][1] = __float_as_uint(hi.x);
                af[m][2] = __float_as_uint(lo.y);
                af[m][3] = __float_as_uint(hi.y);
            }
            #pragma unroll
            for (int n = 0; n < 4; n++) {
                float2 b2 = *(const float2*)&sB[(wn * 32 + n * 8 + g) * SA + kk * 8 + 2 * t4];
                bf[n][0] = __float_as_uint(b2.x);          // b0 (k=t4, n=g)
                bf[n][1] = __float_as_uint(b2.y);          // b1 (k=t4+4, n=g)
            }
            #pragma unroll
            for (int m = 0; m < 4; m++)
                #pragma unroll
                for (int n = 0; n < 4; n++)
                    mma_tf32(acc[m][n], af[m], bf[n]);
        }
        __syncthreads();
    }

    // epilogue: c0,c1 at (row g, cols 2t4,2t4+1); c2,c3 at row g+8
    #pragma unroll
    for (int m = 0; m < 4; m++) {
        int r0 = rowBase + wm * 64 + m * 16 + g;
        #pragma unroll
        for (int n = 0; n < 4; n++) {
            int col = colBase + wn * 32 + n * 8 + 2 * t4;
            #pragma unroll
            for (int h = 0; h < 2; h++) {
                int r = r0 + h * 8;
                float e0 = acc[m][n][2 * h + 0];
                float e1 = acc[m][n][2 * h + 1];
                if (EPI == 1) {
                    float2 bb = *(const float2*)(bias + col);
                    e0 += bb.x;
                    e1 += bb.y;
                    e0 = (e0 > 20.f) ? e0 : log1pf(__expf(e0));
                    e1 = (e1 > 20.f) ? e1 : log1pf(__expf(e1));
                } else if (EPI == 2) {
                    float2 gp = *(const float2*)(g_mod + (r >> 11) * 3 * DM + 2 * DM + col);
                    float2 rp = *(const float2*)(res + (size_t)r * ldc + col);
                    e0 = rp.x + gp.x * e0;
                    e1 = rp.y + gp.y * e1;
                }
                float2 v2;
                v2.x = e0;
                v2.y = e1;
                *(float2*)(C + (size_t)r * ldc + col) = v2;
            }
        }
    }
}

// ---------------- fp32 SGEMM kept for the skinny N=96 projection ----------------
template <int BM, int BN, int BK, int TM, int TN>
__global__ __launch_bounds__((BM / TM) * (BN / TN))
void sgemm(int M, int N, int K, int lda, int ldb, int ldc,
           const float* __restrict__ A, const float* __restrict__ B,
           float* __restrict__ C) {
    constexpr int THREADS = (BM / TM) * (BN / TN);
    __shared__ float As[BK][BM];
    __shared__ float Bs[BK][BN];
    const int tid = threadIdx.x;
    const int tx = tid % (BN / TN);
    const int ty = tid / (BN / TN);
    const int rowBase = blockIdx.y * BM;
    const int colBase = blockIdx.x * BN;
    const float* Ablk = A + (size_t)rowBase * lda;
    const float* Bblk = B + colBase;
    float acc[TM][TN];
    #pragma unroll
    for (int i = 0; i < TM; i++)
        #pragma unroll
        for (int j = 0; j < TN; j++) acc[i][j] = 0.f;

    for (int k0 = 0; k0 < K; k0 += BK) {
        #pragma unroll
        for (int i = tid; i < BM * BK / 4; i += THREADS) {
            int m  = i / (BK / 4);
            int kk = (i % (BK / 4)) * 4;
            float4 v = *(const float4*)(Ablk + (size_t)m * lda + k0 + kk);
            As[kk + 0][m] = v.x;
            As[kk + 1][m] = v.y;
            As[kk + 2][m] = v.z;
            As[kk + 3][m] = v.w;
        }
        #pragma unroll
        for (int i = tid; i < BK * BN / 4; i += THREADS) {
            int kk = i / (BN / 4);
            int n  = (i % (BN / 4)) * 4;
            *(float4*)(&Bs[kk][n]) = *(const float4*)(Bblk + (size_t)(k0 + kk) * ldb + n);
        }
        __syncthreads();
        #pragma unroll
        for (int kk = 0; kk < BK; kk++) {
            float rav[TM], rbv[TN];
            #pragma unroll
            for (int i = 0; i < TM; i++) rav[i] = As[kk][ty * TM + i];
            #pragma unroll
            for (int j = 0; j < TN; j++) rbv[j] = Bs[kk][tx * TN + j];
            #pragma unroll
            for (int i = 0; i < TM; i++)
                #pragma unroll
                for (int j = 0; j < TN; j++)
                    acc[i][j] = fmaf(rav[i], rbv[j], acc[i][j]);
        }
        __syncthreads();
    }
    #pragma unroll
    for (int i = 0; i < TM; i++) {
        int r = rowBase + ty * TM + i;
        #pragma unroll
        for (int j = 0; j < TN; j++) {
            int n = colBase + tx * TN + j;
            C[(size_t)r * ldc + n] = acc[i][j];
        }
    }
}

// ---------------- launch ----------------
extern "C" void kernel_launch(void* const* d_in, const int* in_sizes, int n_in,
                              void* d_out, int out_size) {
    const float* x      = (const float*)d_in[0];
    const float* c      = (const float*)d_in[1];
    const float* W_in   = (const float*)d_in[2];
    const float* conv_w = (const float*)d_in[3];
    const float* conv_b = (const float*)d_in[4];
    const float* W_xp   = (const float*)d_in[5];
    const float* W_dt   = (const float*)d_in[6];
    const float* b_dt   = (const float*)d_in[7];
    const float* A_log  = (const float*)d_in[8];
    const float* D_skip = (const float*)d_in[9];
    const float* W_out  = (const float*)d_in[10];
    const float* W_ada  = (const float*)d_in[11];
    const float* b_ada  = (const float*)d_in[12];
    float* out = (float*)d_out;

    float *p_h, *p_xz, *p_xc, *p_dbc, *p_delta, *p_ymul, *p_WinT, *p_WdtT, *p_WoutT;
    cudaGetSymbolAddress((void**)&p_h,     g_h);
    cudaGetSymbolAddress((void**)&p_xz,    g_xz);
    cudaGetSymbolAddress((void**)&p_xc,    g_xc);
    cudaGetSymbolAddress((void**)&p_dbc,   g_dbc);
    cudaGetSymbolAddress((void**)&p_delta, g_delta);
    cudaGetSymbolAddress((void**)&p_ymul,  g_ymul);
    cudaGetSymbolAddress((void**)&p_WinT,  g_WinT);
    cudaGetSymbolAddress((void**)&p_WdtT,  g_WdtT);
    cudaGetSymbolAddress((void**)&p_WoutT, g_WoutT);

    // 0) weight transposes to [N][K] K-major (mma B operand is col-major)
    k_tr<<<dim3(2 * DI / 32, DM / 32), dim3(32, 8)>>>(W_in,  p_WinT,  DM, 2 * DI);
    k_tr<<<dim3(DI / 32, DTR / 32),    dim3(32, 8)>>>(W_dt,  p_WdtT,  DTR, DI);
    k_tr<<<dim3(DM / 32, DI / 32),     dim3(32, 8)>>>(W_out, p_WoutT, DI, DM);

    // 1) silu(c), ada modulation
    k_silu_c<<<(Bb * DM + 255) / 256, 256>>>(c);
    k_ada<<<dim3(3 * DM / 256, Bb), 256>>>(W_ada, b_ada);

    // 2) LayerNorm + scale/shift
    k_ln<<<ROWS, 256>>>(x);

    // 3) GEMM1 (tf32 mma): h @ W_in -> xz   [8192 x 4096, K=1024]
    gemm_mma<0><<<dim3(2 * DI / 128, ROWS / 128), 256>>>(
        DM, DM, DM, 2 * DI, p_h, p_WinT, p_xz, nullptr, nullptr);

    // 4) depthwise causal conv + silu -> xc
    k_conv<<<(ROWS * DI) / 256, 256>>>(conv_w, conv_b);

    // 5) GEMM2 (fp32, skinny): xc @ W_xproj -> dbc   [8192 x 96, K=2048]
    sgemm<64, 96, 16, 4, 6><<<dim3(1, ROWS / 64), 256>>>(
        ROWS, DBC, DI, DI, DBC, DBC, p_xc, W_xp, p_dbc);

    // 6) delta GEMM (tf32 mma): dbc[:, :64] @ W_dt + b_dt, softplus -> delta [8192 x 2048, K=64]
    gemm_mma<1><<<dim3(DI / 128, ROWS / 128), 256>>>(
        DTR, DBC, DTR, DI, p_dbc, p_WdtT, p_delta, b_dt, nullptr);

    // 7) selective scan (4-way state split) + skip + silu(z) gate -> ymul
    k_scan4<<<(4 * ROWS) / 256, 256>>>(A_log, D_skip);

    // 8) GEMM3 (tf32 mma): ymul @ W_out, fused residual + gate -> out [8192 x 1024, K=2048]
    gemm_mma<2><<<dim3(DM / 128, ROWS / 128), 256>>>(
        DI, DI, DI, DM, p_ymul, p_WoutT, out, nullptr, x);
}

// round 9
// speedup vs baseline: 1.4315x; 1.2482x over previous
#include <cuda_runtime.h>
#include <cstdint>
#include <cstddef>

// ---------------- problem constants ----------------
static constexpr int Bb  = 4;
static constexpr int L   = 2048;
static constexpr int DM  = 1024;          // d_model
static constexpr int DI  = 2048;          // d_inner
static constexpr int DS  = 16;            // d_state
static constexpr int DTR = 64;            // dt_rank
static constexpr int ROWS = Bb * L;       // 8192
static constexpr int DBC = DTR + 2 * DS;  // 96

// ---------------- scratch (device globals, no allocations) ----------------
__device__ float g_sc[Bb * DM];                         // silu(c)
__device__ float g_mod[Bb * 3 * DM];                    // scale|shift|gate
__device__ float g_h[(size_t)ROWS * DM];                // LN-modulated input
__device__ float g_xz[(size_t)ROWS * 2 * DI];           // x@W_in  (xm | z)
__device__ float g_xc[(size_t)ROWS * DI];               // conv+silu
__device__ float g_dbc[(size_t)ROWS * DBC];             // dt | B | C
__device__ float g_delta[(size_t)ROWS * DI];            // softplus(dt@W_dt+b)
__device__ float g_ymul[(size_t)ROWS * DI];             // (scan + u*D)*silu(z)
__device__ float g_WinT[(size_t)(2 * DI) * DM];         // W_in^T  [4096][1024]
__device__ float g_WdtT[(size_t)DI * DTR];              // W_dt^T  [2048][64]
__device__ float g_WoutT[(size_t)DM * DI];              // W_out^T [1024][2048]

// ---------------- helpers ----------------
__device__ __forceinline__ uint32_t smem_u32(const void* p) {
    uint32_t a;
    asm("{ .reg .u64 t; cvta.to.shared.u64 t, %1; cvt.u32.u64 %0, t; }" : "=r"(a) : "l"(p));
    return a;
}
__device__ __forceinline__ void cp_async16(uint32_t dst, const void* src) {
    asm volatile("cp.async.cg.shared.global [%0], [%1], 16;"
                 :: "r"(dst), "l"(__cvta_generic_to_global(src)));
}
#define CP_COMMIT() asm volatile("cp.async.commit_group;" ::: "memory")
#define CP_WAIT1()  asm volatile("cp.async.wait_group 1;" ::: "memory")

__device__ __forceinline__ void mma_tf32(float* c, const uint32_t* a, const uint32_t* b) {
    asm volatile(
        "mma.sync.aligned.m16n8k8.row.col.f32.tf32.tf32.f32 "
        "{%0,%1,%2,%3}, {%4,%5,%6,%7}, {%8,%9}, {%0,%1,%2,%3};"
        : "+f"(c[0]), "+f"(c[1]), "+f"(c[2]), "+f"(c[3])
        : "r"(a[0]), "r"(a[1]), "r"(a[2]), "r"(a[3]), "r"(b[0]), "r"(b[1]));
}

// ---------------- small kernels ----------------
__global__ void k_silu_c(const float* __restrict__ c) {
    int i = blockIdx.x * blockDim.x + threadIdx.x;
    if (i < Bb * DM) {
        float v = c[i];
        g_sc[i] = v / (1.f + __expf(-v));
    }
}

__global__ void k_ada(const float* __restrict__ W, const float* __restrict__ bias) {
    int j = blockIdx.x * blockDim.x + threadIdx.x;
    int b = blockIdx.y;
    const float* sc = g_sc + b * DM;
    float a0 = 0.f, a1 = 0.f, a2 = 0.f, a3 = 0.f;
    for (int k = 0; k < DM; k += 4) {
        a0 += sc[k]     * W[(size_t)k       * (3 * DM) + j];
        a1 += sc[k + 1] * W[(size_t)(k + 1) * (3 * DM) + j];
        a2 += sc[k + 2] * W[(size_t)(k + 2) * (3 * DM) + j];
        a3 += sc[k + 3] * W[(size_t)(k + 3) * (3 * DM) + j];
    }
    g_mod[b * 3 * DM + j] = bias[j] + ((a0 + a1) + (a2 + a3));
}

__global__ void k_ln(const float* __restrict__ x) {
    int row = blockIdx.x;
    int b = row >> 11;
    const float4* xr = (const float4*)(x + (size_t)row * DM);
    float4 v = xr[threadIdx.x];
    float s = v.x + v.y + v.z + v.w;
    float q = v.x * v.x + v.y * v.y + v.z * v.z + v.w * v.w;
    #pragma unroll
    for (int o = 16; o; o >>= 1) {
        s += __shfl_xor_sync(0xffffffffu, s, o);
        q += __shfl_xor_sync(0xffffffffu, q, o);
    }
    __shared__ float ss[8], sq[8];
    int w = threadIdx.x >> 5;
    if ((threadIdx.x & 31) == 0) { ss[w] = s; sq[w] = q; }
    __syncthreads();
    s = 0.f; q = 0.f;
    #pragma unroll
    for (int i = 0; i < 8; i++) { s += ss[i]; q += sq[i]; }
    float mean = s * (1.f / DM);
    float var  = q * (1.f / DM) - mean * mean;
    float rstd = rsqrtf(var + 1e-6f);
    int col = threadIdx.x * 4;
    float4 sc4 = *(const float4*)(g_mod + b * 3 * DM + col);
    float4 sh4 = *(const float4*)(g_mod + b * 3 * DM + DM + col);
    float4 o;
    o.x = (v.x - mean) * rstd * (1.f + sc4.x) + sh4.x;
    o.y = (v.y - mean) * rstd * (1.f + sc4.y) + sh4.y;
    o.z = (v.z - mean) * rstd * (1.f + sc4.z) + sh4.z;
    o.w = (v.w - mean) * rstd * (1.f + sc4.w) + sh4.w;
    *(float4*)(g_h + (size_t)row * DM + col) = o;
}

__global__ void k_conv(const float* __restrict__ cw, const float* __restrict__ cb) {
    int i = blockIdx.x * blockDim.x + threadIdx.x;
    if (i >= ROWS * DI) return;
    int d = i & (DI - 1);
    int row = i >> 11;
    int l = row & (L - 1);
    float4 w = *(const float4*)(cw + 4 * d);
    size_t base = (size_t)row * (2 * DI) + d;
    float acc = cb[d] + g_xz[base] * w.w;
    if (l >= 1) acc += g_xz[base - 1 * (2 * DI)] * w.z;
    if (l >= 2) acc += g_xz[base - 2 * (2 * DI)] * w.y;
    if (l >= 3) acc += g_xz[base - 3 * (2 * DI)] * w.x;
    float sil = acc / (1.f + __expf(-acc));
    g_xc[(size_t)row * DI + d] = sil;
}

// 32x32 tiled transpose: D[C][R] = S[R][C]^T
__global__ void k_tr(const float* __restrict__ S, float* __restrict__ D, int R, int C) {
    __shared__ float t[32][33];
    int c0 = blockIdx.x * 32, r0 = blockIdx.y * 32;
    #pragma unroll
    for (int j = 0; j < 4; j++)
        t[threadIdx.y + 8 * j][threadIdx.x] =
            S[(size_t)(r0 + threadIdx.y + 8 * j) * C + c0 + threadIdx.x];
    __syncthreads();
    #pragma unroll
    for (int j = 0; j < 4; j++)
        D[(size_t)(c0 + threadIdx.y + 8 * j) * R + r0 + threadIdx.x] =
            t[threadIdx.x][threadIdx.y + 8 * j];
}

// selective scan: 4 threads per (b,d) channel, 4 states each.
__global__ void k_scan4(const float* __restrict__ Alog, const float* __restrict__ Dskip) {
    int t = blockIdx.x * blockDim.x + threadIdx.x;   // 0..32767
    int q = t & 3;
    int ch = t >> 2;                                 // 0..8191
    int b = ch >> 11, d = ch & (DI - 1);
    float Ar[4];
    #pragma unroll
    for (int s = 0; s < 4; s++) Ar[s] = -__expf(Alog[d * DS + q * 4 + s]);
    float h[4] = {0.f, 0.f, 0.f, 0.f};
    float Dsk = Dskip[d];
    const float* dbcB = g_dbc + (size_t)(b * L) * DBC + DTR + q * 4;
    size_t base = (size_t)(b * L) * DI + d;
    size_t zb   = (size_t)(b * L) * (2 * DI) + DI + d;
    for (int l = 0; l < L; l++) {
        float delta = g_delta[base];
        float u     = g_xc[base];
        float4 Bv = *(const float4*)(dbcB + (size_t)l * DBC);
        float4 Cv = *(const float4*)(dbcB + (size_t)l * DBC + DS);
        float du = delta * u;
        float y = 0.f;
        float dA0 = __expf(delta * Ar[0]);
        float dA1 = __expf(delta * Ar[1]);
        float dA2 = __expf(delta * Ar[2]);
        float dA3 = __expf(delta * Ar[3]);
        h[0] = fmaf(dA0, h[0], du * Bv.x); y = fmaf(h[0], Cv.x, y);
        h[1] = fmaf(dA1, h[1], du * Bv.y); y = fmaf(h[1], Cv.y, y);
        h[2] = fmaf(dA2, h[2], du * Bv.z); y = fmaf(h[2], Cv.z, y);
        h[3] = fmaf(dA3, h[3], du * Bv.w); y = fmaf(h[3], Cv.w, y);
        y += __shfl_xor_sync(0xffffffffu, y, 1);
        y += __shfl_xor_sync(0xffffffffu, y, 2);
        if (q == 0) {
            float z = g_xz[zb];
            float yy = y + u * Dsk;
            float sig = 1.f / (1.f + __expf(-z));
            g_ymul[base] = yy * (z * sig);
        }
        base += DI;
        zb   += 2 * DI;
    }
}

// ---------------- tf32 mma.sync GEMM, cp.async 3-stage pipeline ----------------
// C[M,N] = A[M,K] * Bt[N,K]^T.  CTA tile 128x128, BK=32, 8 warps each 64x32.
// smem per stage: A 128x32 fp32 + B 128x32 fp32, XOR-swizzled rows
// (float offset = r*32 + ((chunk ^ (r&7))<<2) + within), chunk = col>>2.
// fp32 fed to mma.tf32 directly (HW truncation; error budget is huge).
// EPI 0: plain   EPI 1: softplus(acc + bias[n])   EPI 2: res + gate*acc
template <int EPI>
__global__ __launch_bounds__(256, 2)
void gemm_mma(int K, int lda, int ldb, int ldc,
              const float* __restrict__ A, const float* __restrict__ Bt,
              float* __restrict__ C,
              const float* __restrict__ bias, const float* __restrict__ res) {
    extern __shared__ float smem[];           // 3 stages x 8192 floats (A|B)
    const int tid = threadIdx.x;
    const int wid = tid >> 5, lane = tid & 31;
    const int g = lane >> 2, t4 = lane & 3;
    const int wm = wid & 1, wn = wid >> 1;
    const int rowBase = blockIdx.y * 128, colBase = blockIdx.x * 128;
    const float* Ab = A  + (size_t)rowBase * lda;
    const float* Bp = Bt + (size_t)colBase * ldb;
    const uint32_t smemB = smem_u32(smem);

    float acc[4][4][4];
    #pragma unroll
    for (int m = 0; m < 4; m++)
        #pragma unroll
        for (int n = 0; n < 4; n++)
            #pragma unroll
            for (int e = 0; e < 4; e++) acc[m][n][e] = 0.f;

    // copy mapping: 4 chunks per thread per operand; idx = tid + i*256
    // r = idx>>3 (0..127), c = idx&7 (16B chunk) -> swizzled dst
    auto issue_stage = [&](int s, int k0) {
        uint32_t sb = smemB + (uint32_t)s * 8192u * 4u;
        #pragma unroll
        for (int i = 0; i < 4; i++) {
            int idx = tid + i * 256;
            int r = idx >> 3, cch = idx & 7;
            uint32_t doff = ((uint32_t)(r * 32 + ((cch ^ (r & 7)) << 2))) * 4u;
            cp_async16(sb + doff, Ab + (size_t)r * lda + k0 + cch * 4);
            cp_async16(sb + 16384u + doff, Bp + (size_t)r * ldb + k0 + cch * 4);
        }
        CP_COMMIT();
    };

    const int nk = K >> 5;                    // K >= 64 always
    issue_stage(0, 0);
    issue_stage(1, 32);

    for (int k = 0; k < nk; k++) {
        CP_WAIT1();
        __syncthreads();
        if (k + 2 < nk) issue_stage((k + 2) % 3, (k + 2) * 32);
        else CP_COMMIT();                     // keep group accounting uniform

        const float* sA = smem + (k % 3) * 8192;
        const float* sB = sA + 4096;
        const int aR = wm * 64 + g;           // A fragment base row
        const int bR = wn * 32 + g;           // B fragment base row
        #pragma unroll
        for (int kk = 0; kk < 4; kk++) {
            const int c0 = (((kk * 2 + 0) ^ g) << 2) + t4;   // swizzled col, chunk kk*2
            const int c1 = (((kk * 2 + 1) ^ g) << 2) + t4;   // swizzled col, chunk kk*2+1
            uint32_t af[4][4], bf[4][2];
            #pragma unroll
            for (int m = 0; m < 4; m++) {
                const float* p = sA + (aR + m * 16) * 32;
                af[m][0] = __float_as_uint(p[c0]);
                af[m][1] = __float_as_uint(p[8 * 32 + c0]);
                af[m][2] = __float_as_uint(p[c1]);
                af[m][3] = __float_as_uint(p[8 * 32 + c1]);
            }
            #pragma unroll
            for (int n = 0; n < 4; n++) {
                const float* p = sB + (bR + n * 8) * 32;
                bf[n][0] = __float_as_uint(p[c0]);
                bf[n][1] = __float_as_uint(p[c1]);
            }
            #pragma unroll
            for (int m = 0; m < 4; m++)
                #pragma unroll
                for (int n = 0; n < 4; n++)
                    mma_tf32(acc[m][n], af[m], bf[n]);
        }
        __syncthreads();
    }

    // epilogue: c0,c1 at (row g, cols 2t4,2t4+1); c2,c3 at row g+8
    #pragma unroll
    for (int m = 0; m < 4; m++) {
        int r0 = rowBase + wm * 64 + m * 16 + g;
        #pragma unroll
        for (int n = 0; n < 4; n++) {
            int col = colBase + wn * 32 + n * 8 + 2 * t4;
            #pragma unroll
            for (int h = 0; h < 2; h++) {
                int r = r0 + h * 8;
                float e0 = acc[m][n][2 * h + 0];
                float e1 = acc[m][n][2 * h + 1];
                if (EPI == 1) {
                    float2 bb = *(const float2*)(bias + col);
                    e0 += bb.x;
                    e1 += bb.y;
                    e0 = (e0 > 20.f) ? e0 : log1pf(__expf(e0));
                    e1 = (e1 > 20.f) ? e1 : log1pf(__expf(e1));
                } else if (EPI == 2) {
                    float2 gp = *(const float2*)(g_mod + (r >> 11) * 3 * DM + 2 * DM + col);
                    float2 rp = *(const float2*)(res + (size_t)r * ldc + col);
                    e0 = rp.x + gp.x * e0;
                    e1 = rp.y + gp.y * e1;
                }
                float2 v2;
                v2.x = e0;
                v2.y = e1;
                *(float2*)(C + (size_t)r * ldc + col) = v2;
            }
        }
    }
}

// ---------------- fp32 SGEMM kept for the skinny N=96 projection ----------------
template <int BM, int BN, int BK, int TM, int TN>
__global__ __launch_bounds__((BM / TM) * (BN / TN))
void sgemm(int M, int N, int K, int lda, int ldb, int ldc,
           const float* __restrict__ A, const float* __restrict__ B,
           float* __restrict__ C) {
    constexpr int THREADS = (BM / TM) * (BN / TN);
    __shared__ float As[BK][BM];
    __shared__ float Bs[BK][BN];
    const int tid = threadIdx.x;
    const int tx = tid % (BN / TN);
    const int ty = tid / (BN / TN);
    const int rowBase = blockIdx.y * BM;
    const int colBase = blockIdx.x * BN;
    const float* Ablk = A + (size_t)rowBase * lda;
    const float* Bblk = B + colBase;
    float acc[TM][TN];
    #pragma unroll
    for (int i = 0; i < TM; i++)
        #pragma unroll
        for (int j = 0; j < TN; j++) acc[i][j] = 0.f;

    for (int k0 = 0; k0 < K; k0 += BK) {
        #pragma unroll
        for (int i = tid; i < BM * BK / 4; i += THREADS) {
            int m  = i / (BK / 4);
            int kk = (i % (BK / 4)) * 4;
            float4 v = *(const float4*)(Ablk + (size_t)m * lda + k0 + kk);
            As[kk + 0][m] = v.x;
            As[kk + 1][m] = v.y;
            As[kk + 2][m] = v.z;
            As[kk + 3][m] = v.w;
        }
        #pragma unroll
        for (int i = tid; i < BK * BN / 4; i += THREADS) {
            int kk = i / (BN / 4);
            int n  = (i % (BN / 4)) * 4;
            *(float4*)(&Bs[kk][n]) = *(const float4*)(Bblk + (size_t)(k0 + kk) * ldb + n);
        }
        __syncthreads();
        #pragma unroll
        for (int kk = 0; kk < BK; kk++) {
            float rav[TM], rbv[TN];
            #pragma unroll
            for (int i = 0; i < TM; i++) rav[i] = As[kk][ty * TM + i];
            #pragma unroll
            for (int j = 0; j < TN; j++) rbv[j] = Bs[kk][tx * TN + j];
            #pragma unroll
            for (int i = 0; i < TM; i++)
                #pragma unroll
                for (int j = 0; j < TN; j++)
                    acc[i][j] = fmaf(rav[i], rbv[j], acc[i][j]);
        }
        __syncthreads();
    }
    #pragma unroll
    for (int i = 0; i < TM; i++) {
        int r = rowBase + ty * TM + i;
        #pragma unroll
        for (int j = 0; j < TN; j++) {
            int n = colBase + tx * TN + j;
            C[(size_t)r * ldc + n] = acc[i][j];
        }
    }
}

// ---------------- launch ----------------
extern "C" void kernel_launch(void* const* d_in, const int* in_sizes, int n_in,
                              void* d_out, int out_size) {
    const float* x      = (const float*)d_in[0];
    const float* c      = (const float*)d_in[1];
    const float* W_in   = (const float*)d_in[2];
    const float* conv_w = (const float*)d_in[3];
    const float* conv_b = (const float*)d_in[4];
    const float* W_xp   = (const float*)d_in[5];
    const float* W_dt   = (const float*)d_in[6];
    const float* b_dt   = (const float*)d_in[7];
    const float* A_log  = (const float*)d_in[8];
    const float* D_skip = (const float*)d_in[9];
    const float* W_out  = (const float*)d_in[10];
    const float* W_ada  = (const float*)d_in[11];
    const float* b_ada  = (const float*)d_in[12];
    float* out = (float*)d_out;

    float *p_h, *p_xz, *p_xc, *p_dbc, *p_delta, *p_ymul, *p_WinT, *p_WdtT, *p_WoutT;
    cudaGetSymbolAddress((void**)&p_h,     g_h);
    cudaGetSymbolAddress((void**)&p_xz,    g_xz);
    cudaGetSymbolAddress((void**)&p_xc,    g_xc);
    cudaGetSymbolAddress((void**)&p_dbc,   g_dbc);
    cudaGetSymbolAddress((void**)&p_delta, g_delta);
    cudaGetSymbolAddress((void**)&p_ymul,  g_ymul);
    cudaGetSymbolAddress((void**)&p_WinT,  g_WinT);
    cudaGetSymbolAddress((void**)&p_WdtT,  g_WdtT);
    cudaGetSymbolAddress((void**)&p_WoutT, g_WoutT);

    constexpr int SMEM_GEMM = 3 * 8192 * sizeof(float);   // 96 KB
    cudaFuncSetAttribute(gemm_mma<0>, cudaFuncAttributeMaxDynamicSharedMemorySize, SMEM_GEMM);
    cudaFuncSetAttribute(gemm_mma<1>, cudaFuncAttributeMaxDynamicSharedMemorySize, SMEM_GEMM);
    cudaFuncSetAttribute(gemm_mma<2>, cudaFuncAttributeMaxDynamicSharedMemorySize, SMEM_GEMM);

    // 0) weight transposes to [N][K] K-major (mma B operand is col-major)
    k_tr<<<dim3(2 * DI / 32, DM / 32), dim3(32, 8)>>>(W_in,  p_WinT,  DM, 2 * DI);
    k_tr<<<dim3(DI / 32, DTR / 32),    dim3(32, 8)>>>(W_dt,  p_WdtT,  DTR, DI);
    k_tr<<<dim3(DM / 32, DI / 32),     dim3(32, 8)>>>(W_out, p_WoutT, DI, DM);

    // 1) silu(c), ada modulation
    k_silu_c<<<(Bb * DM + 255) / 256, 256>>>(c);
    k_ada<<<dim3(3 * DM / 256, Bb), 256>>>(W_ada, b_ada);

    // 2) LayerNorm + scale/shift
    k_ln<<<ROWS, 256>>>(x);

    // 3) GEMM1 (tf32 mma): h @ W_in -> xz   [8192 x 4096, K=1024]
    gemm_mma<0><<<dim3(2 * DI / 128, ROWS / 128), 256, SMEM_GEMM>>>(
        DM, DM, DM, 2 * DI, p_h, p_WinT, p_xz, nullptr, nullptr);

    // 4) depthwise causal conv + silu -> xc
    k_conv<<<(ROWS * DI) / 256, 256>>>(conv_w, conv_b);

    // 5) GEMM2 (fp32, skinny): xc @ W_xproj -> dbc   [8192 x 96, K=2048]
    sgemm<64, 96, 16, 4, 6><<<dim3(1, ROWS / 64), 256>>>(
        ROWS, DBC, DI, DI, DBC, DBC, p_xc, W_xp, p_dbc);

    // 6) delta GEMM (tf32 mma): dbc[:, :64] @ W_dt + b_dt, softplus -> delta [8192 x 2048, K=64]
    gemm_mma<1><<<dim3(DI / 128, ROWS / 128), 256, SMEM_GEMM>>>(
        DTR, DBC, DTR, DI, p_dbc, p_WdtT, p_delta, b_dt, nullptr);

    // 7) selective scan (4-way state split) + skip + silu(z) gate -> ymul
    k_scan4<<<(4 * ROWS) / 256, 256>>>(A_log, D_skip);

    // 8) GEMM3 (tf32 mma): ymul @ W_out, fused residual + gate -> out [8192 x 1024, K=2048]
    gemm_mma<2><<<dim3(DM / 128, ROWS / 128), 256, SMEM_GEMM>>>(
        DI, DI, DI, DM, p_ymul, p_WoutT, out, nullptr, x);
}

// round 11
// speedup vs baseline: 1.5556x; 1.0867x over previous
#include <cuda_runtime.h>
#include <cuda_bf16.h>
#include <cstdint>
#include <cstddef>

// ---------------- problem constants ----------------
static constexpr int Bb  = 4;
static constexpr int L   = 2048;
static constexpr int DM  = 1024;          // d_model
static constexpr int DI  = 2048;          // d_inner
static constexpr int DS  = 16;            // d_state
static constexpr int DTR = 64;            // dt_rank
static constexpr int ROWS = Bb * L;       // 8192
static constexpr int DBC = DTR + 2 * DS;  // 96

// ---------------- scratch (device globals, no allocations) ----------------
__device__ float g_sc[Bb * DM];                         // silu(c)
__device__ float g_mod[Bb * 3 * DM];                    // scale|shift|gate
__device__ __nv_bfloat16 g_hh[(size_t)ROWS * DM];       // LN-modulated input (bf16)
__device__ float g_xz[(size_t)ROWS * 2 * DI];           // x@W_in  (xm | z)
__device__ float g_xc[(size_t)ROWS * DI];               // conv+silu
__device__ float g_dbc[(size_t)ROWS * DBC];             // dt | B | C
__device__ float g_delta[(size_t)ROWS * DI];            // softplus(dt@W_dt+b)
__device__ __nv_bfloat16 g_ymulh[(size_t)ROWS * DI];    // (scan+u*D)*silu(z) (bf16)
__device__ __nv_bfloat16 g_WinTh[(size_t)(2 * DI) * DM];// W_in^T  bf16 [4096][1024]
__device__ float g_WdtT[(size_t)DI * DTR];              // W_dt^T  fp32 [2048][64]
__device__ __nv_bfloat16 g_WoutTh[(size_t)DM * DI];     // W_out^T bf16 [1024][2048]

// ---------------- helpers ----------------
__device__ __forceinline__ uint32_t smem_u32(const void* p) {
    uint32_t a;
    asm("{ .reg .u64 t; cvta.to.shared.u64 t, %1; cvt.u32.u64 %0, t; }" : "=r"(a) : "l"(p));
    return a;
}
__device__ __forceinline__ void cp_async16(uint32_t dst, const void* src) {
    asm volatile("cp.async.cg.shared.global [%0], [%1], 16;"
                 :: "r"(dst), "l"(__cvta_generic_to_global(src)));
}
#define CP_COMMIT() asm volatile("cp.async.commit_group;" ::: "memory")
#define CP_WAIT1()  asm volatile("cp.async.wait_group 1;" ::: "memory")

__device__ __forceinline__ void mma_tf32(float* c, const uint32_t* a, const uint32_t* b) {
    asm volatile(
        "mma.sync.aligned.m16n8k8.row.col.f32.tf32.tf32.f32 "
        "{%0,%1,%2,%3}, {%4,%5,%6,%7}, {%8,%9}, {%0,%1,%2,%3};"
        : "+f"(c[0]), "+f"(c[1]), "+f"(c[2]), "+f"(c[3])
        : "r"(a[0]), "r"(a[1]), "r"(a[2]), "r"(a[3]), "r"(b[0]), "r"(b[1]));
}
__device__ __forceinline__ void mma_bf16(float* c, const uint32_t* a, const uint32_t* b) {
    asm volatile(
        "mma.sync.aligned.m16n8k16.row.col.f32.bf16.bf16.f32 "
        "{%0,%1,%2,%3}, {%4,%5,%6,%7}, {%8,%9}, {%0,%1,%2,%3};"
        : "+f"(c[0]), "+f"(c[1]), "+f"(c[2]), "+f"(c[3])
        : "r"(a[0]), "r"(a[1]), "r"(a[2]), "r"(a[3]), "r"(b[0]), "r"(b[1]));
}

// ---------------- small kernels ----------------
__global__ void k_silu_c(const float* __restrict__ c) {
    int i = blockIdx.x * blockDim.x + threadIdx.x;
    if (i < Bb * DM) {
        float v = c[i];
        g_sc[i] = v / (1.f + __expf(-v));
    }
}

__global__ void k_ada(const float* __restrict__ W, const float* __restrict__ bias) {
    int j = blockIdx.x * blockDim.x + threadIdx.x;
    int b = blockIdx.y;
    const float* sc = g_sc + b * DM;
    float a0 = 0.f, a1 = 0.f, a2 = 0.f, a3 = 0.f;
    for (int k = 0; k < DM; k += 4) {
        a0 += sc[k]     * W[(size_t)k       * (3 * DM) + j];
        a1 += sc[k + 1] * W[(size_t)(k + 1) * (3 * DM) + j];
        a2 += sc[k + 2] * W[(size_t)(k + 2) * (3 * DM) + j];
        a3 += sc[k + 3] * W[(size_t)(k + 3) * (3 * DM) + j];
    }
    g_mod[b * 3 * DM + j] = bias[j] + ((a0 + a1) + (a2 + a3));
}

// LayerNorm + (1+scale)*xn + shift -> g_hh (bf16)
__global__ void k_ln(const float* __restrict__ x) {
    int row = blockIdx.x;
    int b = row >> 11;
    const float4* xr = (const float4*)(x + (size_t)row * DM);
    float4 v = xr[threadIdx.x];
    float s = v.x + v.y + v.z + v.w;
    float q = v.x * v.x + v.y * v.y + v.z * v.z + v.w * v.w;
    #pragma unroll
    for (int o = 16; o; o >>= 1) {
        s += __shfl_xor_sync(0xffffffffu, s, o);
        q += __shfl_xor_sync(0xffffffffu, q, o);
    }
    __shared__ float ss[8], sq[8];
    int w = threadIdx.x >> 5;
    if ((threadIdx.x & 31) == 0) { ss[w] = s; sq[w] = q; }
    __syncthreads();
    s = 0.f; q = 0.f;
    #pragma unroll
    for (int i = 0; i < 8; i++) { s += ss[i]; q += sq[i]; }
    float mean = s * (1.f / DM);
    float var  = q * (1.f / DM) - mean * mean;
    float rstd = rsqrtf(var + 1e-6f);
    int col = threadIdx.x * 4;
    float4 sc4 = *(const float4*)(g_mod + b * 3 * DM + col);
    float4 sh4 = *(const float4*)(g_mod + b * 3 * DM + DM + col);
    float o0 = (v.x - mean) * rstd * (1.f + sc4.x) + sh4.x;
    float o1 = (v.y - mean) * rstd * (1.f + sc4.y) + sh4.y;
    float o2 = (v.z - mean) * rstd * (1.f + sc4.z) + sh4.z;
    float o3 = (v.w - mean) * rstd * (1.f + sc4.w) + sh4.w;
    __nv_bfloat162 h0 = __floats2bfloat162_rn(o0, o1);
    __nv_bfloat162 h1 = __floats2bfloat162_rn(o2, o3);
    uint2 u;
    u.x = *(uint32_t*)&h0;
    u.y = *(uint32_t*)&h1;
    *(uint2*)(g_hh + (size_t)row * DM + col) = u;
}

__global__ void k_conv(const float* __restrict__ cw, const float* __restrict__ cb) {
    int i = blockIdx.x * blockDim.x + threadIdx.x;
    if (i >= ROWS * DI) return;
    int d = i & (DI - 1);
    int row = i >> 11;
    int l = row & (L - 1);
    float4 w = *(const float4*)(cw + 4 * d);
    size_t base = (size_t)row * (2 * DI) + d;
    float acc = cb[d] + g_xz[base] * w.w;
    if (l >= 1) acc += g_xz[base - 1 * (2 * DI)] * w.z;
    if (l >= 2) acc += g_xz[base - 2 * (2 * DI)] * w.y;
    if (l >= 3) acc += g_xz[base - 3 * (2 * DI)] * w.x;
    float sil = acc / (1.f + __expf(-acc));
    g_xc[(size_t)row * DI + d] = sil;
}

// 32x32 tiled transpose: fp32 out
__global__ void k_tr(const float* __restrict__ S, float* __restrict__ D, int R, int C) {
    __shared__ float t[32][33];
    int c0 = blockIdx.x * 32, r0 = blockIdx.y * 32;
    #pragma unroll
    for (int j = 0; j < 4; j++)
        t[threadIdx.y + 8 * j][threadIdx.x] =
            S[(size_t)(r0 + threadIdx.y + 8 * j) * C + c0 + threadIdx.x];
    __syncthreads();
    #pragma unroll
    for (int j = 0; j < 4; j++)
        D[(size_t)(c0 + threadIdx.y + 8 * j) * R + r0 + threadIdx.x] =
            t[threadIdx.x][threadIdx.y + 8 * j];
}

// 32x32 tiled transpose: bf16 out
__global__ void k_tr_bf(const float* __restrict__ S, __nv_bfloat16* __restrict__ D, int R, int C) {
    __shared__ float t[32][33];
    int c0 = blockIdx.x * 32, r0 = blockIdx.y * 32;
    #pragma unroll
    for (int j = 0; j < 4; j++)
        t[threadIdx.y + 8 * j][threadIdx.x] =
            S[(size_t)(r0 + threadIdx.y + 8 * j) * C + c0 + threadIdx.x];
    __syncthreads();
    #pragma unroll
    for (int j = 0; j < 4; j++)
        D[(size_t)(c0 + threadIdx.y + 8 * j) * R + r0 + threadIdx.x] =
            __float2bfloat16_rn(t[threadIdx.x][threadIdx.y + 8 * j]);
}

// selective scan: 4 threads per (b,d) channel, 4 states each. bf16 output.
__global__ void k_scan4(const float* __restrict__ Alog, const float* __restrict__ Dskip) {
    int t = blockIdx.x * blockDim.x + threadIdx.x;   // 0..32767
    int q = t & 3;
    int ch = t >> 2;                                 // 0..8191
    int b = ch >> 11, d = ch & (DI - 1);
    float Ar[4];
    #pragma unroll
    for (int s = 0; s < 4; s++) Ar[s] = -__expf(Alog[d * DS + q * 4 + s]);
    float h[4] = {0.f, 0.f, 0.f, 0.f};
    float Dsk = Dskip[d];
    const float* dbcB = g_dbc + (size_t)(b * L) * DBC + DTR + q * 4;
    size_t base = (size_t)(b * L) * DI + d;
    size_t zb   = (size_t)(b * L) * (2 * DI) + DI + d;
    #pragma unroll 2
    for (int l = 0; l < L; l++) {
        float delta = g_delta[base];
        float u     = g_xc[base];
        float4 Bv = *(const float4*)(dbcB + (size_t)l * DBC);
        float4 Cv = *(const float4*)(dbcB + (size_t)l * DBC + DS);
        float du = delta * u;
        float y = 0.f;
        float dA0 = __expf(delta * Ar[0]);
        float dA1 = __expf(delta * Ar[1]);
        float dA2 = __expf(delta * Ar[2]);
        float dA3 = __expf(delta * Ar[3]);
        h[0] = fmaf(dA0, h[0], du * Bv.x); y = fmaf(h[0], Cv.x, y);
        h[1] = fmaf(dA1, h[1], du * Bv.y); y = fmaf(h[1], Cv.y, y);
        h[2] = fmaf(dA2, h[2], du * Bv.z); y = fmaf(h[2], Cv.z, y);
        h[3] = fmaf(dA3, h[3], du * Bv.w); y = fmaf(h[3], Cv.w, y);
        y += __shfl_xor_sync(0xffffffffu, y, 1);
        y += __shfl_xor_sync(0xffffffffu, y, 2);
        if (q == 0) {
            float z = g_xz[zb];
            float yy = y + u * Dsk;
            float sig = 1.f / (1.f + __expf(-z));
            g_ymulh[base] = __float2bfloat16_rn(yy * (z * sig));
        }
        base += DI;
        zb   += 2 * DI;
    }
}

// ---------------- bf16 mma.sync GEMM, cp.async 3-stage pipeline ----------------
// C[M,N](fp32) = A[M,K](bf16) * Bt[N,K](bf16)^T.  CTA tile 128x128, BK=32.
// smem per stage: A 128 rows x 80B (64B data + 16B pad), B same. Padded 80B
// stride => fragment LDS.32 banks (20*r + ...) mod 32 conflict-free.
// EPI 0: plain   EPI 2: res + gate*acc
template <int EPI>
__global__ __launch_bounds__(256, 2)
void gemm_bf16(int K, int lda, int ldb, int ldc,
               const __nv_bfloat16* __restrict__ A, const __nv_bfloat16* __restrict__ Bt,
               float* __restrict__ C,
               const float* __restrict__ res) {
    extern __shared__ char smc[];             // 3 stages x 20480 B (A|B)
    const int tid = threadIdx.x;
    const int wid = tid >> 5, lane = tid & 31;
    const int g = lane >> 2, t4 = lane & 3;
    const int wm = wid & 1, wn = wid >> 1;
    const int rowBase = blockIdx.y * 128, colBase = blockIdx.x * 128;
    const __nv_bfloat16* Ab = A  + (size_t)rowBase * lda;
    const __nv_bfloat16* Bp = Bt + (size_t)colBase * ldb;
    const uint32_t smemB = smem_u32(smc);

    float acc[4][4][4];
    #pragma unroll
    for (int m = 0; m < 4; m++)
        #pragma unroll
        for (int n = 0; n < 4; n++)
            #pragma unroll
            for (int e = 0; e < 4; e++) acc[m][n][e] = 0.f;

    // fill: 512 16B chunks per operand per stage; 2 per thread per operand
    auto issue_stage = [&](int s, int k0) {
        uint32_t sb = smemB + (uint32_t)s * 20480u;
        #pragma unroll
        for (int i = 0; i < 2; i++) {
            int idx = tid + i * 256;
            int r = idx >> 2, ch = idx & 3;
            uint32_t doff = (uint32_t)(r * 80 + ch * 16);
            cp_async16(sb + doff, Ab + (size_t)r * lda + k0 + ch * 8);
            cp_async16(sb + 10240u + doff, Bp + (size_t)r * ldb + k0 + ch * 8);
        }
        CP_COMMIT();
    };

    const int nk = K >> 5;
    issue_stage(0, 0);
    issue_stage(1, 32);

    for (int k = 0; k < nk; k++) {
        CP_WAIT1();
        __syncthreads();
        if (k + 2 < nk) issue_stage((k + 2) % 3, (k + 2) * 32);
        else CP_COMMIT();

        const char* sAc = smc + (k % 3) * 20480;
        const char* sBc = sAc + 10240;
        const int aR = wm * 64 + g;
        const int bR = wn * 32 + g;
        #pragma unroll
        for (int s = 0; s < 2; s++) {          // two k16 steps per BK=32
            uint32_t af[4][4], bf[4][2];
            #pragma unroll
            for (int m = 0; m < 4; m++) {
                const char* p = sAc + (aR + m * 16) * 80 + s * 32 + 4 * t4;
                af[m][0] = *(const uint32_t*)p;             // row g,   k 2t4..+1
                af[m][1] = *(const uint32_t*)(p + 8 * 80);  // row g+8
                af[m][2] = *(const uint32_t*)(p + 16);      // row g,   k +8
                af[m][3] = *(const uint32_t*)(p + 8 * 80 + 16);
            }
            #pragma unroll
            for (int n = 0; n < 4; n++) {
                const char* p = sBc + (bR + n * 8) * 80 + s * 32 + 4 * t4;
                bf[n][0] = *(const uint32_t*)p;             // col g, k 2t4..+1
                bf[n][1] = *(const uint32_t*)(p + 16);      // col g, k +8
            }
            #pragma unroll
            for (int m = 0; m < 4; m++)
                #pragma unroll
                for (int n = 0; n < 4; n++)
                    mma_bf16(acc[m][n], af[m], bf[n]);
        }
        __syncthreads();
    }

    // epilogue: c0,c1 at (row g, cols 2t4,2t4+1); c2,c3 at row g+8
    #pragma unroll
    for (int m = 0; m < 4; m++) {
        int r0 = rowBase + wm * 64 + m * 16 + g;
        #pragma unroll
        for (int n = 0; n < 4; n++) {
            int col = colBase + wn * 32 + n * 8 + 2 * t4;
            #pragma unroll
            for (int h = 0; h < 2; h++) {
                int r = r0 + h * 8;
                float e0 = acc[m][n][2 * h + 0];
                float e1 = acc[m][n][2 * h + 1];
                if (EPI == 2) {
                    float2 gp = *(const float2*)(g_mod + (r >> 11) * 3 * DM + 2 * DM + col);
                    float2 rp = *(const float2*)(res + (size_t)r * ldc + col);
                    e0 = rp.x + gp.x * e0;
                    e1 = rp.y + gp.y * e1;
                }
                float2 v2;
                v2.x = e0;
                v2.y = e1;
                *(float2*)(C + (size_t)r * ldc + col) = v2;
            }
        }
    }
}

// ---------------- tf32 mma.sync GEMM (fp32 in), kept for delta GEMM ----------------
// EPI 1: softplus(acc + bias[n])
template <int EPI>
__global__ __launch_bounds__(256, 2)
void gemm_mma(int K, int lda, int ldb, int ldc,
              const float* __restrict__ A, const float* __restrict__ Bt,
              float* __restrict__ C,
              const float* __restrict__ bias) {
    extern __shared__ float smem[];           // 3 stages x 8192 floats (A|B)
    const int tid = threadIdx.x;
    const int wid = tid >> 5, lane = tid & 31;
    const int g = lane >> 2, t4 = lane & 3;
    const int wm = wid & 1, wn = wid >> 1;
    const int rowBase = blockIdx.y * 128, colBase = blockIdx.x * 128;
    const float* Ab = A  + (size_t)rowBase * lda;
    const float* Bp = Bt + (size_t)colBase * ldb;
    const uint32_t smemB = smem_u32(smem);

    float acc[4][4][4];
    #pragma unroll
    for (int m = 0; m < 4; m++)
        #pragma unroll
        for (int n = 0; n < 4; n++)
            #pragma unroll
            for (int e = 0; e < 4; e++) acc[m][n][e] = 0.f;

    auto issue_stage = [&](int s, int k0) {
        uint32_t sb = smemB + (uint32_t)s * 8192u * 4u;
        #pragma unroll
        for (int i = 0; i < 4; i++) {
            int idx = tid + i * 256;
            int r = idx >> 3, cch = idx & 7;
            uint32_t doff = ((uint32_t)(r * 32 + ((cch ^ (r & 7)) << 2))) * 4u;
            cp_async16(sb + doff, Ab + (size_t)r * lda + k0 + cch * 4);
            cp_async16(sb + 16384u + doff, Bp + (size_t)r * ldb + k0 + cch * 4);
        }
        CP_COMMIT();
    };

    const int nk = K >> 5;
    issue_stage(0, 0);
    issue_stage(1, 32);

    for (int k = 0; k < nk; k++) {
        CP_WAIT1();
        __syncthreads();
        if (k + 2 < nk) issue_stage((k + 2) % 3, (k + 2) * 32);
        else CP_COMMIT();

        const float* sA = smem + (k % 3) * 8192;
        const float* sB = sA + 4096;
        const int aR = wm * 64 + g;
        const int bR = wn * 32 + g;
        #pragma unroll
        for (int kk = 0; kk < 4; kk++) {
            const int c0 = (((kk * 2 + 0) ^ g) << 2) + t4;
            const int c1 = (((kk * 2 + 1) ^ g) << 2) + t4;
            uint32_t af[4][4], bf[4][2];
            #pragma unroll
            for (int m = 0; m < 4; m++) {
                const float* p = sA + (aR + m * 16) * 32;
                af[m][0] = __float_as_uint(p[c0]);
                af[m][1] = __float_as_uint(p[8 * 32 + c0]);
                af[m][2] = __float_as_uint(p[c1]);
                af[m][3] = __float_as_uint(p[8 * 32 + c1]);
            }
            #pragma unroll
            for (int n = 0; n < 4; n++) {
                const float* p = sB + (bR + n * 8) * 32;
                bf[n][0] = __float_as_uint(p[c0]);
                bf[n][1] = __float_as_uint(p[c1]);
            }
            #pragma unroll
            for (int m = 0; m < 4; m++)
                #pragma unroll
                for (int n = 0; n < 4; n++)
                    mma_tf32(acc[m][n], af[m], bf[n]);
        }
        __syncthreads();
    }

    #pragma unroll
    for (int m = 0; m < 4; m++) {
        int r0 = rowBase + wm * 64 + m * 16 + g;
        #pragma unroll
        for (int n = 0; n < 4; n++) {
            int col = colBase + wn * 32 + n * 8 + 2 * t4;
            #pragma unroll
            for (int h = 0; h < 2; h++) {
                int r = r0 + h * 8;
                float e0 = acc[m][n][2 * h + 0];
                float e1 = acc[m][n][2 * h + 1];
                if (EPI == 1) {
                    float2 bb = *(const float2*)(bias + col);
                    e0 += bb.x;
                    e1 += bb.y;
                    e0 = (e0 > 20.f) ? e0 : log1pf(__expf(e0));
                    e1 = (e1 > 20.f) ? e1 : log1pf(__expf(e1));
                }
                float2 v2;
                v2.x = e0;
                v2.y = e1;
                *(float2*)(C + (size_t)r * ldc + col) = v2;
            }
        }
    }
}

// ---------------- fp32 SGEMM kept for the skinny N=96 projection ----------------
template <int BM, int BN, int BK, int TM, int TN>
__global__ __launch_bounds__((BM / TM) * (BN / TN))
void sgemm(int M, int N, int K, int lda, int ldb, int ldc,
           const float* __restrict__ A, const float* __restrict__ B,
           float* __restrict__ C) {
    constexpr int THREADS = (BM / TM) * (BN / TN);
    __shared__ float As[BK][BM];
    __shared__ float Bs[BK][BN];
    const int tid = threadIdx.x;
    const int tx = tid % (BN / TN);
    const int ty = tid / (BN / TN);
    const int rowBase = blockIdx.y * BM;
    const int colBase = blockIdx.x * BN;
    const float* Ablk = A + (size_t)rowBase * lda;
    const float* Bblk = B + colBase;
    float acc[TM][TN];
    #pragma unroll
    for (int i = 0; i < TM; i++)
        #pragma unroll
        for (int j = 0; j < TN; j++) acc[i][j] = 0.f;

    for (int k0 = 0; k0 < K; k0 += BK) {
        #pragma unroll
        for (int i = tid; i < BM * BK / 4; i += THREADS) {
            int m  = i / (BK / 4);
            int kk = (i % (BK / 4)) * 4;
            float4 v = *(const float4*)(Ablk + (size_t)m * lda + k0 + kk);
            As[kk + 0][m] = v.x;
            As[kk + 1][m] = v.y;
            As[kk + 2][m] = v.z;
            As[kk + 3][m] = v.w;
        }
        #pragma unroll
        for (int i = tid; i < BK * BN / 4; i += THREADS) {
            int kk = i / (BN / 4);
            int n  = (i % (BN / 4)) * 4;
            *(float4*)(&Bs[kk][n]) = *(const float4*)(Bblk + (size_t)(k0 + kk) * ldb + n);
        }
        __syncthreads();
        #pragma unroll
        for (int kk = 0; kk < BK; kk++) {
            float rav[TM], rbv[TN];
            #pragma unroll
            for (int i = 0; i < TM; i++) rav[i] = As[kk][ty * TM + i];
            #pragma unroll
            for (int j = 0; j < TN; j++) rbv[j] = Bs[kk][tx * TN + j];
            #pragma unroll
            for (int i = 0; i < TM; i++)
                #pragma unroll
                for (int j = 0; j < TN; j++)
                    acc[i][j] = fmaf(rav[i], rbv[j], acc[i][j]);
        }
        __syncthreads();
    }
    #pragma unroll
    for (int i = 0; i < TM; i++) {
        int r = rowBase + ty * TM + i;
        #pragma unroll
        for (int j = 0; j < TN; j++) {
            int n = colBase + tx * TN + j;
            C[(size_t)r * ldc + n] = acc[i][j];
        }
    }
}

// ---------------- launch ----------------
extern "C" void kernel_launch(void* const* d_in, const int* in_sizes, int n_in,
                              void* d_out, int out_size) {
    const float* x      = (const float*)d_in[0];
    const float* c      = (const float*)d_in[1];
    const float* W_in   = (const float*)d_in[2];
    const float* conv_w = (const float*)d_in[3];
    const float* conv_b = (const float*)d_in[4];
    const float* W_xp   = (const float*)d_in[5];
    const float* W_dt   = (const float*)d_in[6];
    const float* b_dt   = (const float*)d_in[7];
    const float* A_log  = (const float*)d_in[8];
    const float* D_skip = (const float*)d_in[9];
    const float* W_out  = (const float*)d_in[10];
    const float* W_ada  = (const float*)d_in[11];
    const float* b_ada  = (const float*)d_in[12];
    float* out = (float*)d_out;

    float *p_xz, *p_xc, *p_dbc, *p_delta, *p_WdtT;
    __nv_bfloat16 *p_hh, *p_ymulh, *p_WinTh, *p_WoutTh;
    cudaGetSymbolAddress((void**)&p_hh,     g_hh);
    cudaGetSymbolAddress((void**)&p_xz,     g_xz);
    cudaGetSymbolAddress((void**)&p_xc,     g_xc);
    cudaGetSymbolAddress((void**)&p_dbc,    g_dbc);
    cudaGetSymbolAddress((void**)&p_delta,  g_delta);
    cudaGetSymbolAddress((void**)&p_ymulh,  g_ymulh);
    cudaGetSymbolAddress((void**)&p_WinTh,  g_WinTh);
    cudaGetSymbolAddress((void**)&p_WdtT,   g_WdtT);
    cudaGetSymbolAddress((void**)&p_WoutTh, g_WoutTh);

    constexpr int SMEM_TF32 = 3 * 8192 * sizeof(float);   // 96 KB
    constexpr int SMEM_BF16 = 3 * 20480;                  // 60 KB
    cudaFuncSetAttribute(gemm_bf16<0>, cudaFuncAttributeMaxDynamicSharedMemorySize, SMEM_BF16);
    cudaFuncSetAttribute(gemm_bf16<2>, cudaFuncAttributeMaxDynamicSharedMemorySize, SMEM_BF16);
    cudaFuncSetAttribute(gemm_mma<1>,  cudaFuncAttributeMaxDynamicSharedMemorySize, SMEM_TF32);

    // 0) weight transposes to [N][K] K-major (mma B operand is col-major)
    k_tr_bf<<<dim3(2 * DI / 32, DM / 32), dim3(32, 8)>>>(W_in,  p_WinTh,  DM, 2 * DI);
    k_tr   <<<dim3(DI / 32, DTR / 32),    dim3(32, 8)>>>(W_dt,  p_WdtT,   DTR, DI);
    k_tr_bf<<<dim3(DM / 32, DI / 32),     dim3(32, 8)>>>(W_out, p_WoutTh, DI, DM);

    // 1) silu(c), ada modulation
    k_silu_c<<<(Bb * DM + 255) / 256, 256>>>(c);
    k_ada<<<dim3(3 * DM / 256, Bb), 256>>>(W_ada, b_ada);

    // 2) LayerNorm + scale/shift -> bf16
    k_ln<<<ROWS, 256>>>(x);

    // 3) GEMM1 (bf16 mma): h @ W_in -> xz   [8192 x 4096, K=1024]
    gemm_bf16<0><<<dim3(2 * DI / 128, ROWS / 128), 256, SMEM_BF16>>>(
        DM, DM, DM, 2 * DI, p_hh, p_WinTh, p_xz, nullptr);

    // 4) depthwise causal conv + silu -> xc
    k_conv<<<(ROWS * DI) / 256, 256>>>(conv_w, conv_b);

    // 5) GEMM2 (fp32, skinny): xc @ W_xproj -> dbc   [8192 x 96, K=2048]
    sgemm<64, 96, 16, 4, 6><<<dim3(1, ROWS / 64), 256>>>(
        ROWS, DBC, DI, DI, DBC, DBC, p_xc, W_xp, p_dbc);

    // 6) delta GEMM (tf32 mma): dbc[:, :64] @ W_dt + b_dt, softplus -> delta [8192 x 2048, K=64]
    gemm_mma<1><<<dim3(DI / 128, ROWS / 128), 256, SMEM_TF32>>>(
        DTR, DBC, DTR, DI, p_dbc, p_WdtT, p_delta, b_dt);

    // 7) selective scan (4-way state split) + skip + silu(z) gate -> ymul (bf16)
    k_scan4<<<(4 * ROWS) / 256, 256>>>(A_log, D_skip);

    // 8) GEMM3 (bf16 mma): ymul @ W_out, fused residual + gate -> out [8192 x 1024, K=2048]
    gemm_bf16<2><<<dim3(DM / 128, ROWS / 128), 256, SMEM_BF16>>>(
        DI, DI, DI, DM, p_ymulh, p_WoutTh, out, x);
}